// round 13
// baseline (speedup 1.0000x reference)
#include <cuda_runtime.h>
#include <cstdint>

#define NB   32
#define H    1024
#define W    1024
#define BH   73
#define BW   73
#define BS   14                  // block stride = 16 - 3 + 1
#define NROWS (NB*BH)            // 2336 flag rows
#define TOTAL (NB*BH*BW)         // 170528

__device__ unsigned long long g_acc;          // low32: count, high32: image-done ctr
__device__ unsigned long long g_img[NB * 16]; // per-image (count, done), 128B apart
__device__ unsigned g_bits[NROWS * 3];        // 73-bit mask per row (slow path only)
__device__ int g_csum[NROWS];
__device__ int g_coff[NROWS];                 // fixup scratch

// ---------------------------------------------------------------------------
// Rare-path fixup (p ~ 2^-244): some window was inactive, so the speculative
// layout (prefix = 73*row) is wrong. Rebuild the whole output from
// g_csum/g_bits with this single CTA. Perf-irrelevant; correctness only.
// ---------------------------------------------------------------------------
__device__ __noinline__ void fixup(float* __restrict__ out, int total) {
    const int t = threadIdx.x;
    const int nthr = blockDim.x;
    if (t == 0) {
        int acc = 0;
        for (int i = 0; i < NROWS; i++) { g_coff[i] = acc; acc += g_csum[i]; }
    }
    __syncthreads();
    for (int g = t; g < TOTAL; g += nthr) {
        int row = g / BW, col = g - (g / BW) * BW;
        int cnt = g_csum[row], off = g_coff[row];
        int below, f;
        if (cnt == BW) { below = col; f = 1; }
        else {
            unsigned w0 = g_bits[row * 3 + 0];
            unsigned w1 = g_bits[row * 3 + 1];
            unsigned w2 = g_bits[row * 3 + 2];
            unsigned lm = (1u << (col & 31)) - 1u;
            if (col < 32)      { below = __popc(w0 & lm);                           f = (w0 >> col) & 1; }
            else if (col < 64) { below = __popc(w0) + __popc(w1 & lm);              f = (w1 >> (col - 32)) & 1; }
            else               { below = __popc(w0) + __popc(w1) + __popc(w2 & lm); f = (w2 >> (col - 64)) & 1; }
        }
        if (f) {
            int pos = off + below;
            int i0 = row / BH;
            out[3 * pos + 0] = (float)i0;
            out[3 * pos + 1] = (float)(row - i0 * BH);
            out[3 * pos + 2] = (float)col;
        } else {
            int pos = total + (g - (off + below));
            out[3 * pos + 0] = (float)NB;
            out[3 * pos + 1] = (float)BH;
            out[3 * pos + 2] = (float)BW;
        }
    }
}

// ---------------------------------------------------------------------------
// Single fused kernel: pad + 16x16/stride14 max-pool + threshold + compact.
// One 256-thread CTA per (n, by) strip (R11 proven shape).
//  1) Speculative output triples at prefix 73*cta, issued in the load shadow.
//  2) Probe: one float4/thread from row by*14; ballot bitmap of hot chunks;
//     window certified active if any fully-contained 4-chunk is hot.
//  3) Undecided windows (p = 2^-12) -> CTA-wide 16-row slow path.
//  4) HIERARCHICAL arrival: level-1 packed atomic on per-image counter
//     (32 lines 128B apart, max 73-deep per address); the 32 image-last CTAs
//     do the only level-2 atomics on g_acc. Global-last CTA writes the count
//     slot, runs fixup if count != TOTAL (never in practice), resets state.
// ---------------------------------------------------------------------------
__global__ __launch_bounds__(256) void fused_kernel(const float* __restrict__ mask,
                                                    float* __restrict__ out,
                                                    int count_idx) {
    const int cta = blockIdx.x;          // n*BH + by
    const int n  = cta / BH;
    const int by = cta - n * BH;
    const int t  = threadIdx.x;
    const int warp = t >> 5, lane = t & 31;

    __shared__ __align__(16) float cm[W];   // slow path only
    __shared__ unsigned sball[9];            // 8 ballot words + zero pad
    __shared__ int s_last;
    __shared__ unsigned s_tot;

    // ---- 1) speculative output triples (no data dependency) ----
    if (t < 3 * BW) {
        int c = t - (t / 3) * 3;
        int p = t / 3;
        float val = (c == 0) ? (float)n : (c == 1) ? (float)by : (float)p;
        out[(size_t)cta * (3 * BW) + t] = val;
    }

    const float4* base4 = (const float4*)(mask + (size_t)n * H * W);

    // ---- 2) probe: one float4 per thread from row by*14 ----
    float4 v = base4[(size_t)(by * BS) * (W / 4) + t];
    int hot = (v.x > 0.5f) | (v.y > 0.5f) | (v.z > 0.5f) | (v.w > 0.5f);
    unsigned bal = __ballot_sync(0xffffffffu, hot);
    if (lane == 0) sball[warp] = bal;
    if (t == 0) sball[8] = 0u;
    __syncthreads();

    int flag = 0;
    if (t < BW) {
        int lo = t * BS - 1; if (lo < 0) lo = 0;
        int hi = t * BS + 14;            // <= 1022, always in range
        int jlo = (lo + 3) >> 2;         // first fully-contained 4-chunk
        int jhi = (hi - 3) >> 2;         // last fully-contained 4-chunk
        int jw = jlo >> 5, jb = jlo & 31;
        unsigned long long w =
            ((unsigned long long)sball[jw + 1] << 32) | (unsigned long long)sball[jw];
        unsigned m = (1u << (jhi - jlo + 1)) - 1u;
        flag = ((w >> jb) & (unsigned long long)m) != 0ull;
    }
    int und = __syncthreads_count(t < BW && !flag);

    int csum;
    if (und == 0) {
        csum = BW;                        // fast path: every window active
    } else {
        // ---- 3) slow path (rare): thread t = column chunk t over 16 rows ----
        const int row0 = by * BS - 1;     // may be -1 (zero pad); row0+15 <= 1022
        {
            const float4* colp = base4 + t;
            float4 m4 = make_float4(0.f, 0.f, 0.f, 0.f);
#pragma unroll 4
            for (int r = 0; r < 16; r++) {
                int real = row0 + r;
                if (real >= 0) {
                    float4 u = colp[(size_t)real * (W / 4)];
                    m4.x = fmaxf(m4.x, u.x); m4.y = fmaxf(m4.y, u.y);
                    m4.z = fmaxf(m4.z, u.z); m4.w = fmaxf(m4.w, u.w);
                }
            }
            ((float4*)cm)[t] = m4;
        }
        __syncthreads();

        int fl = 0;
        if (t < BW) {
            float mx = 0.f;
            int c0 = t * BS - 1;
#pragma unroll
            for (int k = 0; k < 16; k++) {
                int c = c0 + k;
                if (c >= 0) mx = fmaxf(mx, cm[c]);   // c <= 1022 guaranteed
            }
            fl = (mx > 0.5f) ? 1 : 0;
        }
        unsigned wb = __ballot_sync(0xffffffffu, fl);  // t<73 guard zeroes rest
        if (lane == 0 && warp < 3) g_bits[cta * 3 + warp] = wb;
        csum = __syncthreads_count(fl);
    }

    // ---- 4) hierarchical arrival ----
    if (t == 0) {
        s_last = 0;
        g_csum[cta] = csum;
        unsigned long long add1 = (unsigned long long)(unsigned)csum | (1ull << 32);
        unsigned long long old1;
        asm volatile("atom.add.release.gpu.u64 %0, [%1], %2;"
                     : "=l"(old1) : "l"(&g_img[n * 16]), "l"(add1) : "memory");
        if ((unsigned)(old1 >> 32) == BH - 1) {          // image-last CTA
            unsigned imgtot = (unsigned)(old1 & 0xffffffffu) + (unsigned)csum;
            unsigned long long add2 = (unsigned long long)imgtot | (1ull << 32);
            unsigned long long old2;
            asm volatile("atom.add.release.gpu.u64 %0, [%1], %2;"
                         : "=l"(old2) : "l"(&g_acc), "l"(add2) : "memory");
            if ((unsigned)(old2 >> 32) == NB - 1) {      // global-last CTA
                s_last = 1;
                s_tot  = (unsigned)(old2 & 0xffffffffu) + imgtot;
            }
        }
    }
    __syncthreads();
    if (!s_last) return;

    // global-last CTA: count slot, rare fixup, reset for next graph replay
    if (t == 0 && count_idx >= 0) out[count_idx] = (float)s_tot;
    if (s_tot != TOTAL) {
        asm volatile("fence.acquire.gpu;" ::: "memory");
        fixup(out, (int)s_tot);
    }
    __syncthreads();
    if (t < NB) g_img[t * 16] = 0ull;
    if (t == 0) g_acc = 0ull;
}

extern "C" void kernel_launch(void* const* d_in, const int* in_sizes, int n_in,
                              void* d_out, int out_size) {
    const float* mask = (const float*)d_in[0];
    float* out = (float*)d_out;

    int count_idx = (out_size > 3 * TOTAL) ? (out_size - 1) : -1;

    fused_kernel<<<NROWS, 256>>>(mask, out, count_idx);
}

// round 14
// speedup vs baseline: 1.2657x; 1.2657x over previous
#include <cuda_runtime.h>
#include <cstdint>

#define NB   32
#define H    1024
#define W    1024
#define BH   73
#define BW   73
#define BS   14                  // block stride = 16 - 3 + 1
#define NROWS (NB*BH)            // 2336 flag rows
#define TOTAL (NB*BH*BW)         // 170528

__device__ unsigned long long g_acc;     // low32: running count, high32: done ctr
__device__ unsigned g_bits[NROWS * 3];   // 73-bit mask per row (slow path only)
__device__ int g_csum[NROWS];

// ---------------------------------------------------------------------------
// Rare-path fixup (p ~ 2^-244): some window was inactive, so the speculative
// layout (prefix = 73*row) is wrong. Rebuild the whole output serially from
// g_csum/g_bits (single thread; never executed in practice, correctness only).
// ---------------------------------------------------------------------------
__device__ __noinline__ void fixup(float* __restrict__ out, int total) {
    int off = 0;
    for (int row = 0; row < NROWS; row++) {
        int cnt = g_csum[row];
        int i0 = row / BH;
        int i1 = row - i0 * BH;
        for (int col = 0; col < BW; col++) {
            int f, below;
            if (cnt == BW) { f = 1; below = col; }
            else {
                unsigned w0 = g_bits[row * 3 + 0];
                unsigned w1 = g_bits[row * 3 + 1];
                unsigned w2 = g_bits[row * 3 + 2];
                unsigned lm = (1u << (col & 31)) - 1u;
                if (col < 32)      { below = __popc(w0 & lm);                           f = (w0 >> col) & 1; }
                else if (col < 64) { below = __popc(w0) + __popc(w1 & lm);              f = (w1 >> (col - 32)) & 1; }
                else               { below = __popc(w0) + __popc(w1) + __popc(w2 & lm); f = (w2 >> (col - 64)) & 1; }
            }
            if (f) {
                int pos = off + below;
                out[3 * pos + 0] = (float)i0;
                out[3 * pos + 1] = (float)i1;
                out[3 * pos + 2] = (float)col;
            } else {
                int g = row * BW + col;
                int pos = total + (g - (off + below));
                out[3 * pos + 0] = (float)NB;
                out[3 * pos + 1] = (float)BH;
                out[3 * pos + 2] = (float)BW;
            }
        }
        off += cnt;
    }
}

// ---------------------------------------------------------------------------
// Single fused kernel: pad + 16x16/stride14 max-pool + threshold + compact.
// One 256-thread CTA per (n, by) strip.
//  1) Probe LDG issued first; speculative output triples (prefix 73*cta)
//     written in its shadow.
//  2) Ballot bitmap of hot 4-chunks; window certified active if any
//     fully-contained chunk is hot (undecided p = 2^-12 per window).
//  3) Undecided -> CTA-wide 16-row slow path.
//  4) FAST RETIREMENT: once csum is known, threads 1..255 exit. Only t0
//     stores csum + does the release-atomic; last CTA's t0 writes the count,
//     (never) runs fixup, resets g_acc for the next graph replay.
// ---------------------------------------------------------------------------
__global__ __launch_bounds__(256) void fused_kernel(const float* __restrict__ mask,
                                                    float* __restrict__ out,
                                                    int count_idx) {
    const int cta = blockIdx.x;          // n*BH + by
    const int n  = cta / BH;
    const int by = cta - n * BH;
    const int t  = threadIdx.x;
    const int warp = t >> 5, lane = t & 31;

    __shared__ __align__(16) float cm[W];   // slow path only
    __shared__ unsigned sball[9];            // 8 ballot words + zero pad

    const float4* base4 = (const float4*)(mask + (size_t)n * H * W);

    // ---- 1) probe load first; spec stores fill its shadow ----
    float4 v = base4[(size_t)(by * BS) * (W / 4) + t];

    if (t < 3 * BW) {
        int c = t - (t / 3) * 3;
        int p = t / 3;
        float val = (c == 0) ? (float)n : (c == 1) ? (float)by : (float)p;
        out[(size_t)cta * (3 * BW) + t] = val;
    }

    // ---- 2) chunk-hot ballot bitmap ----
    int hot = (v.x > 0.5f) | (v.y > 0.5f) | (v.z > 0.5f) | (v.w > 0.5f);
    unsigned bal = __ballot_sync(0xffffffffu, hot);
    if (lane == 0) sball[warp] = bal;
    if (t == 0) sball[8] = 0u;
    __syncthreads();

    int flag = 0;
    if (t < BW) {
        int lo = t * BS - 1; if (lo < 0) lo = 0;
        int hi = t * BS + 14;            // <= 1022, always in range
        int jlo = (lo + 3) >> 2;         // first fully-contained 4-chunk
        int jhi = (hi - 3) >> 2;         // last fully-contained 4-chunk
        int jw = jlo >> 5, jb = jlo & 31;
        unsigned long long w =
            ((unsigned long long)sball[jw + 1] << 32) | (unsigned long long)sball[jw];
        unsigned m = (1u << (jhi - jlo + 1)) - 1u;
        flag = ((w >> jb) & (unsigned long long)m) != 0ull;
    }
    int und = __syncthreads_count(t < BW && !flag);

    int csum;
    if (und == 0) {
        csum = BW;                        // fast path: every window active
    } else {
        // ---- 3) slow path (rare): thread t = column chunk t over 16 rows ----
        const int row0 = by * BS - 1;     // may be -1 (zero pad); row0+15 <= 1022
        {
            const float4* colp = base4 + t;
            float4 m4 = make_float4(0.f, 0.f, 0.f, 0.f);
#pragma unroll 4
            for (int r = 0; r < 16; r++) {
                int real = row0 + r;
                if (real >= 0) {
                    float4 u = colp[(size_t)real * (W / 4)];
                    m4.x = fmaxf(m4.x, u.x); m4.y = fmaxf(m4.y, u.y);
                    m4.z = fmaxf(m4.z, u.z); m4.w = fmaxf(m4.w, u.w);
                }
            }
            ((float4*)cm)[t] = m4;
        }
        __syncthreads();

        int fl = 0;
        if (t < BW) {
            float mx = 0.f;
            int c0 = t * BS - 1;
#pragma unroll
            for (int k = 0; k < 16; k++) {
                int c = c0 + k;
                if (c >= 0) mx = fmaxf(mx, cm[c]);   // c <= 1022 guaranteed
            }
            fl = (mx > 0.5f) ? 1 : 0;
        }
        unsigned wb = __ballot_sync(0xffffffffu, fl);  // t<73 guard zeroes rest
        if (lane == 0 && warp < 3) g_bits[cta * 3 + warp] = wb;
        csum = __syncthreads_count(fl);
    }

    // ---- 4) fast retirement: everyone but t0 leaves now ----
    if (t != 0) return;

    g_csum[cta] = csum;
    unsigned long long add = (unsigned long long)(unsigned)csum | (1ull << 32);
    unsigned long long old;
    asm volatile("atom.add.release.gpu.u64 %0, [%1], %2;"
                 : "=l"(old) : "l"(&g_acc), "l"(add) : "memory");
    if ((unsigned)(old >> 32) == NROWS - 1) {        // global-last CTA
        unsigned tot = (unsigned)(old & 0xffffffffu) + (unsigned)csum;
        if (count_idx >= 0) out[count_idx] = (float)tot;
        if (tot != TOTAL) {
            asm volatile("fence.acquire.gpu;" ::: "memory");
            fixup(out, (int)tot);
        }
        g_acc = 0ull;                                // reset for next replay
    }
}

extern "C" void kernel_launch(void* const* d_in, const int* in_sizes, int n_in,
                              void* d_out, int out_size) {
    const float* mask = (const float*)d_in[0];
    float* out = (float*)d_out;

    int count_idx = (out_size > 3 * TOTAL) ? (out_size - 1) : -1;

    fused_kernel<<<NROWS, 256>>>(mask, out, count_idx);
}